// round 15
// baseline (speedup 1.0000x reference)
#include <cuda_runtime.h>
#include <cstdint>

// R=16, C=256, B=12(==H), E=768, H=12, D=64
#define HN       144
#define OUT_ELEMS 37748736
#define PROBS_ELEMS 9437184

// ===== scratch: all GEMM operands stored as tf32 words in fragment "F-tile" layout =====
// F-tile = 2048 words for a (128 row x 16 k) tile:
//   t16=row>>4, r8=(row>>3)&1, lr=row&7 ; kt=k>>3, kh=(k>>2)&1, lc=k&3
//   lane' = lr*4 + ((lc ^ (lr>>1) ^ t16)&3)
//   v'    = (2*kh + r8) ^ (((kt ^ (t16&1))&1)<<1)
//   word  = (t16*2+kt)*128 + lane'*4 + v'
__device__ unsigned g_x_f[37748736];   // x     [mtile384][kc48][2048]
__device__ unsigned g_w_f[2359296];    // Wq/Wk/Wv/Wo [z*6+ntile][kc48][2048]
__device__ unsigned g_q_f[37748736];   // q     [hn*2+itile][kc64][2048]
__device__ unsigned g_k_f[37748736];   // k     [hn*2+jtile][kc64][2048]
__device__ unsigned g_v_f[37748736];   // v     [hn*8+rdtile][kc16][2048]
__device__ float    g_s[9437184];      // scores row-major [hn][i][j]
__device__ unsigned g_p_f[9437184];    // probs [hn*2+itile][kc16][2048]
__device__ unsigned g_ctx_f[37748736]; // ctx   [mtile384][kc48][2048]

__device__ __forceinline__ unsigned f2tf(float x) {
    unsigned u;
    asm("cvt.rna.tf32.f32 %0, %1;" : "=r"(u) : "f"(x));
    return u;
}

__device__ __forceinline__ void mma_tf32(float* c, const unsigned* a, const unsigned* b) {
    asm volatile(
        "mma.sync.aligned.m16n8k8.row.col.f32.tf32.tf32.f32 "
        "{%0,%1,%2,%3}, {%4,%5,%6,%7}, {%8,%9}, {%0,%1,%2,%3};"
        : "+f"(c[0]), "+f"(c[1]), "+f"(c[2]), "+f"(c[3])
        : "r"(a[0]), "r"(a[1]), "r"(a[2]), "r"(a[3]), "r"(b[0]), "r"(b[1]));
}

__device__ __forceinline__ void cp_async16(unsigned* dst, const unsigned* src) {
    unsigned saddr = (unsigned)__cvta_generic_to_shared(dst);
    asm volatile("cp.async.cg.shared.global [%0], [%1], 16;" :: "r"(saddr), "l"(src));
}
__device__ __forceinline__ void cp_commit() {
    asm volatile("cp.async.commit_group;");
}
__device__ __forceinline__ void cp_wait1() {
    asm volatile("cp.async.wait_group 1;");
}

// word index inside an F-tile for (row 0..127, k 0..15)
__device__ __forceinline__ int fword(int row, int k) {
    int t16 = row >> 4, r8 = (row >> 3) & 1, lr = row & 7;
    int kt = k >> 3, kh = (k >> 2) & 1, lc = k & 3;
    int lane = lr * 4 + ((lc ^ (lr >> 1) ^ t16) & 3);
    int v = (2 * kh + r8) ^ (((kt ^ (t16 & 1)) & 1) << 1);
    return (t16 * 2 + kt) * 128 + lane * 4 + v;
}

// ===================== compute =====================
__device__ __forceinline__ void compute16(const unsigned* __restrict__ SA,
                                          const unsigned* __restrict__ SB,
                                          float (*acc)[4][4],
                                          const int* __restrict__ oA,
                                          const int* __restrict__ oB) {
#pragma unroll
    for (int kt = 0; kt < 2; kt++) {
        unsigned a[4][4], b[2][4];
#pragma unroll
        for (int mt = 0; mt < 4; mt++) {
            const uint4 q = *(const uint4*)(SA + oA[mt] + kt * 128);
            if ((kt ^ mt) & 1) { a[mt][0] = q.z; a[mt][1] = q.w; a[mt][2] = q.x; a[mt][3] = q.y; }
            else               { a[mt][0] = q.x; a[mt][1] = q.y; a[mt][2] = q.z; a[mt][3] = q.w; }
        }
#pragma unroll
        for (int np = 0; np < 2; np++) {
            const uint4 q = *(const uint4*)(SB + oB[np] + kt * 128);
            if ((kt ^ np) & 1) { b[np][0] = q.z; b[np][1] = q.w; b[np][2] = q.x; b[np][3] = q.y; }
            else               { b[np][0] = q.x; b[np][1] = q.y; b[np][2] = q.z; b[np][3] = q.w; }
        }
#pragma unroll
        for (int mt = 0; mt < 4; mt++)
#pragma unroll
            for (int np = 0; np < 2; np++) {
                unsigned b0[2] = {b[np][0], b[np][2]};
                unsigned b1[2] = {b[np][1], b[np][3]};
                mma_tf32(acc[mt][2 * np],     a[mt], b0);
                mma_tf32(acc[mt][2 * np + 1], a[mt], b1);
            }
    }
}

#define ACC_INIT float acc[4][4][4]; \
    _Pragma("unroll") for (int _a = 0; _a < 4; _a++) \
    _Pragma("unroll") for (int _b = 0; _b < 4; _b++) \
    _Pragma("unroll") for (int _c = 0; _c < 4; _c++) acc[_a][_b][_c] = 0.f;

#define PREP_OFFS int oA[4], oB[2]; \
    _Pragma("unroll") for (int _m = 0; _m < 4; _m++) { \
        int _l = (lane & 28) | ((lane ^ (lane >> 3) ^ _m) & 3); \
        oA[_m] = (wm * 4 + _m) * 256 + _l * 4; } \
    _Pragma("unroll") for (int _n = 0; _n < 2; _n++) { \
        int _l = (lane & 28) | ((lane ^ (lane >> 3) ^ ((wn & 1) * 2 + _n)) & 3); \
        oB[_n] = (wn * 2 + _n) * 256 + _l * 4; }

// Stage = 32-K chunk = 2 F-tiles per operand (4096 words). 3-stage cp.async pipeline.
// Dynamic smem: SA = smem[0..3*4096), SB = smem[3*4096..6*4096). 96KB total.
#define STAGE_WORDS 4096
#define SMEM_BYTES  98304

__device__ __forceinline__ void stage_issue(const unsigned* __restrict__ A,
                                            const unsigned* __restrict__ B,
                                            unsigned* SA, unsigned* SB,
                                            int c2, int stage, int w8) {
    const unsigned* As = A + c2 * STAGE_WORDS;
    const unsigned* Bs = B + c2 * STAGE_WORDS;
    unsigned* sa = SA + stage * STAGE_WORDS;
    unsigned* sb = SB + stage * STAGE_WORDS;
    cp_async16(sa + w8, As + w8);
    cp_async16(sa + w8 + 4, As + w8 + 4);
    cp_async16(sa + 2048 + w8, As + 2048 + w8);
    cp_async16(sa + 2048 + w8 + 4, As + 2048 + w8 + 4);
    cp_async16(sb + w8, Bs + w8);
    cp_async16(sb + w8 + 4, Bs + w8 + 4);
    cp_async16(sb + 2048 + w8, Bs + 2048 + w8);
    cp_async16(sb + 2048 + w8 + 4, Bs + 2048 + w8 + 4);
}

// nk2 = number of 32-K chunks.
__device__ __forceinline__ void gemm_f(const unsigned* __restrict__ A,
                                       const unsigned* __restrict__ B,
                                       int nk2, int t, float (*acc)[4][4],
                                       unsigned* SA, unsigned* SB,
                                       const int* oA, const int* oB) {
    const int w8 = t * 8;
#pragma unroll
    for (int s = 0; s < 2; s++) {
        if (s < nk2) stage_issue(A, B, SA, SB, s, s, w8);
        cp_commit();
    }
    int buf = 0;
    for (int c = 0; c < nk2; c++) {
        cp_wait1();
        __syncthreads();
        if (c + 2 < nk2) {
            int nb = buf + 2; if (nb >= 3) nb -= 3;
            stage_issue(A, B, SA, SB, c + 2, nb, w8);
        }
        cp_commit();
        const unsigned* sa = SA + buf * STAGE_WORDS;
        const unsigned* sb = SB + buf * STAGE_WORDS;
        compute16(sa, sb, acc, oA, oB);
        compute16(sa + 2048, sb + 2048, acc, oA, oB);
        if (++buf == 3) buf = 0;
    }
    __syncthreads();
}

// -------------------- Kernel 0: convert x / W's into F-layout tf32 --------------------
__global__ __launch_bounds__(256)
void k_prep(const float* __restrict__ x,
            const float* __restrict__ Wq, const float* __restrict__ Wk,
            const float* __restrict__ Wv, const float* __restrict__ Wo) {
    const int bb = blockIdx.x;
    const float* src;
    unsigned* dst;
    int row0, k0;
    if (bb < 18432) {                       // x: mtile(384) x kc(48)
        int mtile = bb / 48, kc = bb - mtile * 48;
        src = x; row0 = mtile * 128; k0 = kc * 16;
        dst = g_x_f + (size_t)bb * 2048;
    } else {                                // W: z(4) x ntile(6) x kc(48)
        int b2 = bb - 18432;
        int z = b2 / 288, rem = b2 - z * 288;
        int ntile = rem / 48, kc = rem - ntile * 48;
        src = (z == 0) ? Wq : (z == 1) ? Wk : (z == 2) ? Wv : Wo;
        row0 = ntile * 128; k0 = kc * 16;
        dst = g_w_f + (size_t)b2 * 2048;
    }
    const int t = threadIdx.x;
    const int row = t >> 1, kt = t & 1;
    const float* p = src + (size_t)(row0 + row) * 768 + k0 + kt * 8;
    float4 f0 = *(const float4*)p, f1 = *(const float4*)(p + 4);
    const int t16 = row >> 4, r8 = (row >> 3) & 1, lr = row & 7;
    const int base = (t16 * 2 + kt) * 128;
    const int vx = ((kt ^ (t16 & 1)) & 1) << 1;
    const float e0[4] = {f0.x, f0.y, f0.z, f0.w};
    const float e1[4] = {f1.x, f1.y, f1.z, f1.w};
#pragma unroll
    for (int j = 0; j < 4; j++) {
        int lane = lr * 4 + ((j ^ (lr >> 1) ^ t16) & 3);
        dst[base + lane * 4 + ((0 + r8) ^ vx)] = f2tf(e0[j]);
        dst[base + lane * 4 + ((2 + r8) ^ vx)] = f2tf(e1[j]);
    }
}

// -------------------- Kernel 1: fused QKV projection --------------------
__global__ __launch_bounds__(256, 2)
void k_qkv(const float* __restrict__ bq, const float* __restrict__ bk,
           const float* __restrict__ bv) {
    const int z = blockIdx.x;
    const float* bias = (z == 0) ? bq : (z == 1) ? bk : bv;
    unsigned* out     = (z == 0) ? g_q_f : (z == 1) ? g_k_f : g_v_f;
    const float scale = (z == 0) ? 0.03125f : 1.0f;

    extern __shared__ unsigned smem[];
    unsigned* SA = smem;
    unsigned* SB = smem + 3 * STAGE_WORDS;

    const int t = threadIdx.x;
    const int lane = t & 31, warp = t >> 5, wm = warp >> 2, wn = warp & 3;
    const int n0 = blockIdx.y * 128;
    const int m0 = blockIdx.z * 128;

    const unsigned* A = g_x_f + (size_t)blockIdx.z * 48 * 2048;
    const unsigned* B = g_w_f + (size_t)((z * 6 + blockIdx.y) * 48) * 2048;

    PREP_OFFS
    ACC_INIT
    gemm_f(A, B, 24, t, acc, SA, SB, oA, oB);

#pragma unroll
    for (int mt = 0; mt < 4; mt++)
#pragma unroll
        for (int nt = 0; nt < 4; nt++)
#pragma unroll
            for (int e = 0; e < 4; e++) {
                int m = m0 + wm * 64 + mt * 16 + (lane >> 2) + ((e >= 2) ? 8 : 0);
                int n = n0 + wn * 32 + nt * 8 + 2 * (lane & 3) + (e & 1);
                int r = m / 3072;
                int rem = m - r * 3072;
                int i = rem / 12;
                int nb = rem - i * 12;
                int h = n >> 6, d = n & 63;
                int hn = h * 12 + nb;
                unsigned w = f2tf((acc[mt][nt][e] + bias[n]) * scale);
                size_t idx;
                if (z < 2)   // q/k: rows=i, k=rd
                    idx = ((size_t)(hn * 2 + (i >> 7)) * 64 + (r * 4 + (d >> 4))) * 2048
                        + fword(i & 127, d & 15);
                else         // v: rows=rd, k=i
                    idx = ((size_t)(hn * 8 + (r >> 1)) * 16 + (i >> 4)) * 2048
                        + fword(((r & 1) << 6) | d, i & 15);
                out[idx] = w;
            }
}

// -------------------- Kernel 2: attention scores --------------------
__global__ __launch_bounds__(256, 2)
void k_scores() {
    const int hn = blockIdx.z;
    const unsigned* A = g_q_f + (size_t)(hn * 2 + blockIdx.x) * 64 * 2048;
    const unsigned* B = g_k_f + (size_t)(hn * 2 + blockIdx.y) * 64 * 2048;

    extern __shared__ unsigned smem[];
    unsigned* SA = smem;
    unsigned* SB = smem + 3 * STAGE_WORDS;

    const int t = threadIdx.x;
    const int lane = t & 31, warp = t >> 5, wm = warp >> 2, wn = warp & 3;
    const int m0 = blockIdx.x * 128;
    const int n0 = blockIdx.y * 128;

    PREP_OFFS
    ACC_INIT
    gemm_f(A, B, 32, t, acc, SA, SB, oA, oB);

#pragma unroll
    for (int mt = 0; mt < 4; mt++)
#pragma unroll
        for (int nt = 0; nt < 4; nt++)
#pragma unroll
            for (int e = 0; e < 4; e++) {
                int m = m0 + wm * 64 + mt * 16 + (lane >> 2) + ((e >= 2) ? 8 : 0);
                int n = n0 + wn * 32 + nt * 8 + 2 * (lane & 3) + (e & 1);
                g_s[((size_t)hn << 16) + m * 256 + n] = acc[mt][nt][e];
            }
}

// -------------------- Kernel 3: bias + softmax --------------------
__global__ __launch_bounds__(256)
void k_softmax(const int* __restrict__ dist, const float* __restrict__ rb,
               float* __restrict__ probs_out) {
    const int bx = blockIdx.x;
    const int hn = bx >> 8;
    const int i = bx & 255;
    const int h = hn / 12;
    const int nb = hn - h * 12;
    const int j = threadIdx.x;
    const int lane = j & 31, warp = j >> 5;

    const size_t sidx = ((size_t)hn << 16) + (i << 8) + j;
    float s = g_s[sidx];

    int dd = dist[((h << 8) + i) * 256 + j];
    int a = dd < 0 ? -dd : dd;
    int bucket;
    if (a < 16) {
        bucket = a;
    } else {
        float nf = (float)a;
        float v = logf(nf * 0.0625f) / 8.047189562170502f * 15.0f;
        bucket = 16 + (int)v;
        if (bucket > 31) bucket = 31;
    }
    s += rb[bucket * 12 + nb];

    __shared__ float red[8];
    float m = s;
#pragma unroll
    for (int o = 16; o > 0; o >>= 1)
        m = fmaxf(m, __shfl_xor_sync(0xffffffffu, m, o));
    if (lane == 0) red[warp] = m;
    __syncthreads();
    float mx = red[0];
#pragma unroll
    for (int w = 1; w < 8; w++) mx = fmaxf(mx, red[w]);
    __syncthreads();

    const float e = expf(s - mx);
    float sum = e;
#pragma unroll
    for (int o = 16; o > 0; o >>= 1)
        sum += __shfl_xor_sync(0xffffffffu, sum, o);
    if (lane == 0) red[warp] = sum;
    __syncthreads();
    float tot = red[0];
#pragma unroll
    for (int w = 1; w < 8; w++) tot += red[w];

    const float p = e / tot;
    if (probs_out) probs_out[sidx] = p;
    g_p_f[((size_t)(hn * 2 + (i >> 7)) * 16 + (j >> 4)) * 2048 + fword(i & 127, j & 15)] = f2tf(p);
}

// -------------------- Kernel 4: context --------------------
__global__ __launch_bounds__(256, 2)
void k_ctx() {
    const int hn = blockIdx.z;
    const unsigned* A = g_p_f + (size_t)(hn * 2 + blockIdx.x) * 16 * 2048;
    const unsigned* B = g_v_f + (size_t)(hn * 8 + blockIdx.y) * 16 * 2048;

    extern __shared__ unsigned smem[];
    unsigned* SA = smem;
    unsigned* SB = smem + 3 * STAGE_WORDS;

    const int t = threadIdx.x;
    const int lane = t & 31, warp = t >> 5, wm = warp >> 2, wn = warp & 3;
    const int m0 = blockIdx.x * 128;   // i
    const int n0 = blockIdx.y * 128;   // rd

    PREP_OFFS
    ACC_INIT
    gemm_f(A, B, 8, t, acc, SA, SB, oA, oB);

    const int h = hn / 12;
    const int nb = hn - h * 12;
#pragma unroll
    for (int mt = 0; mt < 4; mt++)
#pragma unroll
        for (int nt = 0; nt < 4; nt++)
#pragma unroll
            for (int e = 0; e < 4; e++) {
                int i = m0 + wm * 64 + mt * 16 + (lane >> 2) + ((e >= 2) ? 8 : 0);
                int n = n0 + wn * 32 + nt * 8 + 2 * (lane & 3) + (e & 1);  // rd
                int r = n >> 6, d = n & 63;
                int mo = (r * 256 + i) * 12 + nb;
                int ec = h * 64 + d;
                g_ctx_f[((size_t)(mo >> 7) * 48 + (ec >> 4)) * 2048 + fword(mo & 127, d & 15)]
                    = f2tf(acc[mt][nt][e]);
            }
}

// -------------------- Kernel 5: output projection --------------------
__global__ __launch_bounds__(256, 2)
void k_out(const float* __restrict__ bo, float* __restrict__ out) {
    extern __shared__ unsigned smem[];
    unsigned* SA = smem;
    unsigned* SB = smem + 3 * STAGE_WORDS;

    const int t = threadIdx.x;
    const int lane = t & 31, warp = t >> 5, wm = warp >> 2, wn = warp & 3;
    const int n0 = blockIdx.x * 128;
    const int m0 = blockIdx.y * 128;

    const unsigned* A = g_ctx_f + (size_t)blockIdx.y * 48 * 2048;
    const unsigned* B = g_w_f + (size_t)((3 * 6 + blockIdx.x) * 48) * 2048;

    PREP_OFFS
    ACC_INIT
    gemm_f(A, B, 24, t, acc, SA, SB, oA, oB);

#pragma unroll
    for (int mt = 0; mt < 4; mt++)
#pragma unroll
        for (int nt = 0; nt < 4; nt++)
#pragma unroll
            for (int e = 0; e < 4; e++) {
                int m = m0 + wm * 64 + mt * 16 + (lane >> 2) + ((e >= 2) ? 8 : 0);
                int n = n0 + wn * 32 + nt * 8 + 2 * (lane & 3) + (e & 1);
                out[(size_t)m * 768 + n] = acc[mt][nt][e] + bo[n];
            }
}

// -------------------- launch --------------------
extern "C" void kernel_launch(void* const* d_in, const int* in_sizes, int n_in,
                              void* d_out, int out_size) {
    const float* x    = (const float*)d_in[0];
    const int*   dist = (const int*)d_in[1];
    const float* Wq   = (const float*)d_in[2];
    const float* bq   = (const float*)d_in[3];
    const float* Wk   = (const float*)d_in[4];
    const float* bk   = (const float*)d_in[5];
    const float* Wv   = (const float*)d_in[6];
    const float* bv   = (const float*)d_in[7];
    const float* Wo   = (const float*)d_in[8];
    const float* bo   = (const float*)d_in[9];
    const float* rb   = (const float*)d_in[10];

    float* out = (float*)d_out;
    float* probs = (out_size >= OUT_ELEMS + PROBS_ELEMS) ? (out + OUT_ELEMS) : nullptr;

    cudaFuncSetAttribute(k_qkv,    cudaFuncAttributeMaxDynamicSharedMemorySize, SMEM_BYTES);
    cudaFuncSetAttribute(k_scores, cudaFuncAttributeMaxDynamicSharedMemorySize, SMEM_BYTES);
    cudaFuncSetAttribute(k_ctx,    cudaFuncAttributeMaxDynamicSharedMemorySize, SMEM_BYTES);
    cudaFuncSetAttribute(k_out,    cudaFuncAttributeMaxDynamicSharedMemorySize, SMEM_BYTES);

    dim3 thr(256);
    k_prep<<<dim3(18432 + 1152), thr>>>(x, Wq, Wk, Wv, Wo);
    k_qkv<<<dim3(3, 6, 384), thr, SMEM_BYTES>>>(bq, bk, bv);
    k_scores<<<dim3(2, 2, HN), thr, SMEM_BYTES>>>();
    k_softmax<<<dim3(HN * 256), thr>>>(dist, rb, probs);
    k_ctx<<<dim3(2, 8, HN), thr, SMEM_BYTES>>>();
    k_out<<<dim3(6, 384), thr, SMEM_BYTES>>>(bo, out);
}